// round 11
// baseline (speedup 1.0000x reference)
#include <cuda_runtime.h>
#include <cuda_fp16.h>
#include <math.h>

#define NN_MAX 100000
#define EE_MAX 1600000
#define DH 64

// ---------------- device scratch ----------------
__device__ __half g_tmph[NN_MAX * DH]; // fp16 messages: (act(X) @ W^T) * dinv
__device__ float g_h[NN_MAX * DH];     // layer activations (pre-BN, post-bias)
__device__ float g_dinv[NN_MAX];
__device__ int   g_counts[NN_MAX];     // zeroed by scan3 after use (self-restoring)
__device__ int   g_rowptr[NN_MAX + 1];
__device__ int   g_cursor[NN_MAX];
__device__ int   g_esrc[EE_MAX];
__device__ int   g_blocksums[128];
__device__ float g_sums[DH];           // zeroed by stats_final after use
__device__ float g_sumsq[DH];
__device__ float g_scale[DH];
__device__ float g_shift[DH];

__device__ __forceinline__ float gelu_f(float v) {
    return 0.5f * v * (1.0f + erff(v * 0.70710678118654752440f));
}

// ---- packed f32x2 helpers (sm_103a FFMA2 path) ----
__device__ __forceinline__ unsigned long long pack2(float x, float y) {
    unsigned long long r;
    asm("mov.b64 %0, {%1, %2};" : "=l"(r) : "f"(x), "f"(y));
    return r;
}
__device__ __forceinline__ void fma2(unsigned long long& d, unsigned long long a,
                                     unsigned long long b) {
    asm("fma.rn.f32x2 %0, %1, %2, %0;" : "+l"(d) : "l"(a), "l"(b));
}
__device__ __forceinline__ float2 unpack2(unsigned long long v) {
    float2 f;
    asm("mov.b64 {%0, %1}, %2;" : "=f"(f.x), "=f"(f.y) : "l"(v));
    return f;
}

// ---------------- CSR build ----------------
__global__ void hist_kernel(const int* __restrict__ dst, int ee) {
    int e = blockIdx.x * blockDim.x + threadIdx.x;
    if (e < ee) atomicAdd(&g_counts[dst[e]], 1);
}

__global__ void scan1_kernel(int nn) {
    __shared__ int s[1024];
    int t = threadIdx.x;
    int i = blockIdx.x * 1024 + t;
    int c = (i < nn) ? g_counts[i] : 0;
    s[t] = c;
    __syncthreads();
    for (int off = 1; off < 1024; off <<= 1) {
        int v = (t >= off) ? s[t - off] : 0;
        __syncthreads();
        s[t] += v;
        __syncthreads();
    }
    if (i < nn) g_rowptr[i] = s[t];
    if (t == 1023) g_blocksums[blockIdx.x] = s[1023];
}

// merged scan2+scan3: finalize rowptr/cursor/dinv, zero counts for next call
__global__ void scan3_kernel(int nn, int ee, int nb) {
    __shared__ int bs[128];
    int t = threadIdx.x;
    if (t < 128) bs[t] = (t < nb) ? g_blocksums[t] : 0;
    __syncthreads();
    for (int off = 1; off < 128; off <<= 1) {
        int v = (t >= off && t < 128) ? bs[t - off] : 0;
        __syncthreads();
        if (t < 128) bs[t] += v;
        __syncthreads();
    }
    int base = (blockIdx.x == 0) ? 0 : bs[blockIdx.x - 1];

    int i = blockIdx.x * 1024 + t;
    if (i < nn) {
        int c = g_counts[i];
        g_counts[i] = 0;
        int excl = g_rowptr[i] - c + base;
        g_rowptr[i] = excl;
        g_cursor[i] = excl;
        g_dinv[i] = rsqrtf((float)(c + 1));  // +1 self loop
    }
    if (i == 0) g_rowptr[nn] = ee;
}

__global__ void fill_kernel(const int* __restrict__ src, const int* __restrict__ dst, int ee) {
    int e = blockIdx.x * blockDim.x + threadIdx.x;
    if (e < ee) {
        int pos = atomicAdd(&g_cursor[dst[e]], 1);
        g_esrc[pos] = src[e];
    }
}

// ---------------- GEMM: g_tmph[n,:] = fp16( (act(X)[n,:] @ W^T) * dinv[n] ) ----------------
// BM=128, BN=64, BK=32; 256 threads; 8x4 tile; FFMA2 packed along m (R10 form).
template <int DIN, bool USE_GH, bool APPLY_ACT>
__global__ __launch_bounds__(256)
void gemm_scale_kernel(const float* __restrict__ Xin,
                       const float* __restrict__ W, int nn) {
    const float* __restrict__ X = USE_GH ? (const float*)g_h : Xin;

    __shared__ float Xs[32][132];  // [k][m], pad 4
    __shared__ float Ws[32][68];   // [k][j], pad 4
    __shared__ float s_sc[DH];
    __shared__ float s_sh[DH];

    int tid = threadIdx.x;
    int br = blockIdx.x * 128;
    int tx = tid & 15;   // col group: j0 = tx*4
    int ty = tid >> 4;   // row group: m0 = ty*8

    if (APPLY_ACT) {
        if (tid < DH) { s_sc[tid] = g_scale[tid]; s_sh[tid] = g_shift[tid]; }
        __syncthreads();
    }

    // accp[im][j]: packed rows (ty*8+2im, ty*8+2im+1), col tx*4+j
    unsigned long long accp[4][4];
#pragma unroll
    for (int i = 0; i < 4; i++)
#pragma unroll
        for (int j = 0; j < 4; j++) accp[i][j] = 0ULL;

    for (int kb = 0; kb < DIN; kb += 32) {
        // X tile: thread -> row = tid>>1, k-half seg = tid&1 (16 floats), transposed store
        {
            int row = br + (tid >> 1);
            int seg = (tid & 1) * 16;
            bool ok = row < nn;
            const float* xr = X + (size_t)row * DIN + kb + seg;
#pragma unroll
            for (int kk = 0; kk < 4; kk++) {
                float4 v = ok ? *(const float4*)(xr + kk * 4)
                              : make_float4(0.f, 0.f, 0.f, 0.f);
                if (APPLY_ACT && ok) {
                    int k0 = kb + seg + kk * 4;
                    v.x = gelu_f(v.x * s_sc[k0 + 0] + s_sh[k0 + 0]);
                    v.y = gelu_f(v.y * s_sc[k0 + 1] + s_sh[k0 + 1]);
                    v.z = gelu_f(v.z * s_sc[k0 + 2] + s_sh[k0 + 2]);
                    v.w = gelu_f(v.w * s_sc[k0 + 3] + s_sh[k0 + 3]);
                }
                int r = tid >> 1;
                Xs[seg + kk * 4 + 0][r] = v.x;
                Xs[seg + kk * 4 + 1][r] = v.y;
                Xs[seg + kk * 4 + 2][r] = v.z;
                Xs[seg + kk * 4 + 3][r] = v.w;
            }
        }
        // W tile: thread -> j = tid&63, k-quarter = (tid>>6)*8, 2 float4
        {
            int j = tid & 63;
            int kh = (tid >> 6) * 8;
            const float* wr = W + (size_t)j * DIN + kb + kh;
#pragma unroll
            for (int kk = 0; kk < 2; kk++) {
                float4 v = *(const float4*)(wr + kk * 4);
                Ws[kh + kk * 4 + 0][j] = v.x;
                Ws[kh + kk * 4 + 1][j] = v.y;
                Ws[kh + kk * 4 + 2][j] = v.z;
                Ws[kh + kk * 4 + 3][j] = v.w;
            }
        }
        __syncthreads();

#pragma unroll 8
        for (int k = 0; k < 32; k++) {
            ulonglong2 A01 = *(const ulonglong2*)&Xs[k][ty * 8];
            ulonglong2 A23 = *(const ulonglong2*)&Xs[k][ty * 8 + 4];
            float4 b = *(const float4*)&Ws[k][tx * 4];
            unsigned long long bb0 = pack2(b.x, b.x);
            unsigned long long bb1 = pack2(b.y, b.y);
            unsigned long long bb2 = pack2(b.z, b.z);
            unsigned long long bb3 = pack2(b.w, b.w);
            fma2(accp[0][0], A01.x, bb0); fma2(accp[0][1], A01.x, bb1);
            fma2(accp[0][2], A01.x, bb2); fma2(accp[0][3], A01.x, bb3);
            fma2(accp[1][0], A01.y, bb0); fma2(accp[1][1], A01.y, bb1);
            fma2(accp[1][2], A01.y, bb2); fma2(accp[1][3], A01.y, bb3);
            fma2(accp[2][0], A23.x, bb0); fma2(accp[2][1], A23.x, bb1);
            fma2(accp[2][2], A23.x, bb2); fma2(accp[2][3], A23.x, bb3);
            fma2(accp[3][0], A23.y, bb0); fma2(accp[3][1], A23.y, bb1);
            fma2(accp[3][2], A23.y, bb2); fma2(accp[3][3], A23.y, bb3);
        }
        __syncthreads();
    }

#pragma unroll
    for (int im = 0; im < 4; im++) {
        float2 c0 = unpack2(accp[im][0]);
        float2 c1 = unpack2(accp[im][1]);
        float2 c2 = unpack2(accp[im][2]);
        float2 c3 = unpack2(accp[im][3]);
        int row0 = br + ty * 8 + 2 * im;
        int row1 = row0 + 1;
        if (row0 < nn) {
            float dv = g_dinv[row0];
            __half2 p0 = __floats2half2_rn(c0.x * dv, c1.x * dv);
            __half2 p1 = __floats2half2_rn(c2.x * dv, c3.x * dv);
            uint2 u;
            u.x = *(unsigned int*)&p0;
            u.y = *(unsigned int*)&p1;
            *(uint2*)&g_tmph[(size_t)row0 * DH + tx * 4] = u;
        }
        if (row1 < nn) {
            float dv = g_dinv[row1];
            __half2 p0 = __floats2half2_rn(c0.y * dv, c1.y * dv);
            __half2 p1 = __floats2half2_rn(c2.y * dv, c3.y * dv);
            uint2 u;
            u.x = *(unsigned int*)&p0;
            u.y = *(unsigned int*)&p1;
            *(uint2*)&g_tmph[(size_t)row1 * DH + tx * 4] = u;
        }
    }
}

// ---------------- gather-aggregate + bias + BN stats ----------------
// warp per node; lane owns columns (2*lane, 2*lane+1) as half2 (row=128B=1 line);
// 8-wide unroll with int4-vectorized index loads; fp32 accumulation.
__global__ void gather_kernel(const float* __restrict__ bias, int nn) {
    __shared__ float ss[DH];
    __shared__ float sq[DH];
    int tid = threadIdx.x;
    if (tid < DH) { ss[tid] = 0.0f; sq[tid] = 0.0f; }
    __syncthreads();

    const __half2* __restrict__ tmp2 = (const __half2*)g_tmph;
    float2* __restrict__ h2 = (float2*)g_h;

    int lane = tid & 31;
    int warp = blockIdx.x * (blockDim.x >> 5) + (tid >> 5);
    int nwarps = gridDim.x * (blockDim.x >> 5);

    float bx = bias[2 * lane];
    float by = bias[2 * lane + 1];
    float s0 = 0.f, s1 = 0.f, q0 = 0.f, q1 = 0.f;

    for (int n = warp; n < nn; n += nwarps) {
        int st = g_rowptr[n];
        int en = g_rowptr[n + 1];
        float2 self = __half22float2(tmp2[n * 32 + lane]);
        float ax = self.x, ay = self.y;
        int e = st;
        // prologue: advance to 16B-aligned index position
        for (; e < en && (e & 3); e++) {
            float2 v = __half22float2(tmp2[g_esrc[e] * 32 + lane]);
            ax += v.x; ay += v.y;
        }
        // main: 8 edges per iter, indices via 2x int4
        for (; e + 8 <= en; e += 8) {
            int4 i0 = *(const int4*)&g_esrc[e];
            int4 i1 = *(const int4*)&g_esrc[e + 4];
            __half2 h0 = tmp2[i0.x * 32 + lane];
            __half2 h1 = tmp2[i0.y * 32 + lane];
            __half2 h2v = tmp2[i0.z * 32 + lane];
            __half2 h3 = tmp2[i0.w * 32 + lane];
            __half2 h4 = tmp2[i1.x * 32 + lane];
            __half2 h5 = tmp2[i1.y * 32 + lane];
            __half2 h6 = tmp2[i1.z * 32 + lane];
            __half2 h7 = tmp2[i1.w * 32 + lane];
            float2 v0 = __half22float2(h0);
            float2 v1 = __half22float2(h1);
            float2 v2 = __half22float2(h2v);
            float2 v3 = __half22float2(h3);
            float2 v4 = __half22float2(h4);
            float2 v5 = __half22float2(h5);
            float2 v6 = __half22float2(h6);
            float2 v7 = __half22float2(h7);
            ax += ((v0.x + v1.x) + (v2.x + v3.x)) + ((v4.x + v5.x) + (v6.x + v7.x));
            ay += ((v0.y + v1.y) + (v2.y + v3.y)) + ((v4.y + v5.y) + (v6.y + v7.y));
        }
        // epilogue
        for (; e < en; e++) {
            float2 v = __half22float2(tmp2[g_esrc[e] * 32 + lane]);
            ax += v.x; ay += v.y;
        }
        float dv = g_dinv[n];
        float rx = ax * dv + bx;
        float ry = ay * dv + by;
        h2[n * 32 + lane] = make_float2(rx, ry);
        s0 += rx; q0 += rx * rx;
        s1 += ry; q1 += ry * ry;
    }

    atomicAdd(&ss[2 * lane], s0);
    atomicAdd(&ss[2 * lane + 1], s1);
    atomicAdd(&sq[2 * lane], q0);
    atomicAdd(&sq[2 * lane + 1], q1);
    __syncthreads();
    if (tid < DH) {
        atomicAdd(&g_sums[tid], ss[tid]);
        atomicAdd(&g_sumsq[tid], sq[tid]);
    }
}

// ---------------- BN stats -> scale/shift; re-zero stats ----------------
__global__ void stats_final_kernel(const float* __restrict__ gamma,
                                   const float* __restrict__ beta, float invN) {
    int j = threadIdx.x;  // 64 threads
    float mean = g_sums[j] * invN;
    float var = g_sumsq[j] * invN - mean * mean;
    float sc = gamma[j] * rsqrtf(var + 1e-5f);
    g_scale[j] = sc;
    g_shift[j] = beta[j] - mean * sc;
    g_sums[j] = 0.0f;
    g_sumsq[j] = 0.0f;
}

// ---------------- final: out = act(h) @ Wf^T + bf  (64 -> 10) ----------------
__global__ void final_kernel(const float* __restrict__ Wf, const float* __restrict__ bf,
                             float* __restrict__ out, int nn) {
    __shared__ float Hs[64][65];
    __shared__ float Ws[10][64];
    __shared__ float s_sc[DH];
    __shared__ float s_sh[DH];
    int tid = threadIdx.x;  // 128 threads
    int br = blockIdx.x * 64;

    if (tid < DH) { s_sc[tid] = g_scale[tid]; s_sh[tid] = g_shift[tid]; }
    __syncthreads();

    for (int idx = tid; idx < 64 * 64; idx += 128) {
        int n = idx >> 6, k = idx & 63;
        int row = br + n;
        float v = (row < nn) ? g_h[row * DH + k] : 0.0f;
        Hs[n][k] = gelu_f(v * s_sc[k] + s_sh[k]);
    }
    for (int idx = tid; idx < 640; idx += 128) {
        Ws[idx >> 6][idx & 63] = Wf[idx];
    }
    __syncthreads();

    int nl = tid & 63;
    int c0 = (tid >> 6) * 5;
    float acc[5];
#pragma unroll
    for (int c = 0; c < 5; c++) acc[c] = bf[c0 + c];
#pragma unroll 16
    for (int k = 0; k < 64; k++) {
        float hv = Hs[nl][k];
#pragma unroll
        for (int c = 0; c < 5; c++) acc[c] += hv * Ws[c0 + c][k];
    }
    int row = br + nl;
    if (row < nn) {
#pragma unroll
        for (int c = 0; c < 5; c++) out[row * 10 + c0 + c] = acc[c];
    }
}

// ---------------- host orchestration ----------------
extern "C" void kernel_launch(void* const* d_in, const int* in_sizes, int n_in,
                              void* d_out, int out_size) {
    const float* x  = (const float*)d_in[0];
    const int*   ei = (const int*)d_in[1];
    const float* W1 = (const float*)d_in[2];
    const float* b1 = (const float*)d_in[3];
    const float* g1 = (const float*)d_in[4];
    const float* be1 = (const float*)d_in[5];
    const float* W2 = (const float*)d_in[6];
    const float* b2 = (const float*)d_in[7];
    const float* g2 = (const float*)d_in[8];
    const float* be2 = (const float*)d_in[9];
    const float* W3 = (const float*)d_in[10];
    const float* b3 = (const float*)d_in[11];
    const float* g3 = (const float*)d_in[12];
    const float* be3 = (const float*)d_in[13];
    const float* Wf = (const float*)d_in[14];
    const float* bf = (const float*)d_in[15];
    float* out = (float*)d_out;

    int nn = in_sizes[0] / 128;      // 100000
    int ee = in_sizes[1] / 2;        // 1600000
    const int* src = ei;
    const int* dst = ei + ee;

    int nb_e = (ee + 255) / 256;
    int nb_scan = (nn + 1023) / 1024;
    float invN = 1.0f / (float)nn;

    int gemm_blocks = (nn + 127) / 128;
    int out_blocks = (nn + 63) / 64;
    int gather_blocks = 1184;

    // ---- CSR build (counts/stats pre-zeroed: self-restoring invariants) ----
    hist_kernel<<<nb_e, 256>>>(dst, ee);
    scan1_kernel<<<nb_scan, 1024>>>(nn);
    scan3_kernel<<<nb_scan, 1024>>>(nn, ee, nb_scan);

    // ---- layer 1 (128 -> 64) ----
    gemm_scale_kernel<128, false, false><<<gemm_blocks, 256>>>(x, W1, nn);
    fill_kernel<<<nb_e, 256>>>(src, dst, ee);
    gather_kernel<<<gather_blocks, 256>>>(b1, nn);
    stats_final_kernel<<<1, 64>>>(g1, be1, invN);

    // ---- layer 2 (64 -> 64): BN1+GELU fused into X load ----
    gemm_scale_kernel<64, true, true><<<gemm_blocks, 256>>>(nullptr, W2, nn);
    gather_kernel<<<gather_blocks, 256>>>(b2, nn);
    stats_final_kernel<<<1, 64>>>(g2, be2, invN);

    // ---- layer 3 (64 -> 64): BN2+GELU fused into X load ----
    gemm_scale_kernel<64, true, true><<<gemm_blocks, 256>>>(nullptr, W3, nn);
    gather_kernel<<<gather_blocks, 256>>>(b3, nn);
    stats_final_kernel<<<1, 64>>>(g3, be3, invN);

    // ---- final classifier (64 -> 10): BN3+GELU fused into H load ----
    final_kernel<<<out_blocks, 128>>>(Wf, bf, out, nn);
}

// round 13
// speedup vs baseline: 1.1686x; 1.1686x over previous
#include <cuda_runtime.h>
#include <cuda_bf16.h>
#include <cstdint>
#include <math.h>

#define NN_MAX 100000
#define EE_MAX 1600000
#define DH 64

// ---------------- device scratch ----------------
__device__ float g_tmp[NN_MAX * DH];   // fp32 messages: (act(X) @ W^T) * dinv
__device__ float g_h[NN_MAX * DH];     // layer activations (pre-BN, post-bias)
__device__ float g_dinv[NN_MAX];
__device__ int   g_counts[NN_MAX];     // zeroed by scan3 after use (self-restoring)
__device__ int   g_rowptr[NN_MAX + 1];
__device__ int   g_cursor[NN_MAX];
__device__ int   g_esrc[EE_MAX];
__device__ int   g_blocksums[128];
__device__ float g_sums[DH];           // zeroed by stats_final after use
__device__ float g_sumsq[DH];
__device__ float g_scale[DH];
__device__ float g_shift[DH];

__device__ __forceinline__ float gelu_f(float v) {
    return 0.5f * v * (1.0f + erff(v * 0.70710678118654752440f));
}

__device__ __forceinline__ unsigned int smem_u32(const void* p) {
    unsigned int a;
    asm("{ .reg .u64 t; cvta.to.shared.u64 t, %1; cvt.u32.u64 %0, t; }"
        : "=r"(a) : "l"(p));
    return a;
}

__device__ __forceinline__ void ldmat4(unsigned int& r0, unsigned int& r1,
                                       unsigned int& r2, unsigned int& r3,
                                       unsigned int addr) {
    asm volatile("ldmatrix.sync.aligned.m8n8.x4.shared.b16 {%0,%1,%2,%3}, [%4];"
                 : "=r"(r0), "=r"(r1), "=r"(r2), "=r"(r3) : "r"(addr));
}

__device__ __forceinline__ void mma16816(float* c, const unsigned int* a,
                                         unsigned int b0, unsigned int b1) {
    asm volatile(
        "mma.sync.aligned.m16n8k16.row.col.f32.bf16.bf16.f32 "
        "{%0,%1,%2,%3}, {%4,%5,%6,%7}, {%8,%9}, {%0,%1,%2,%3};"
        : "+f"(c[0]), "+f"(c[1]), "+f"(c[2]), "+f"(c[3])
        : "r"(a[0]), "r"(a[1]), "r"(a[2]), "r"(a[3]), "r"(b0), "r"(b1));
}

// ---------------- CSR build ----------------
__global__ void hist_kernel(const int* __restrict__ dst, int ee) {
    int e = blockIdx.x * blockDim.x + threadIdx.x;
    if (e < ee) atomicAdd(&g_counts[dst[e]], 1);
}

__global__ void scan1_kernel(int nn) {
    __shared__ int s[1024];
    int t = threadIdx.x;
    int i = blockIdx.x * 1024 + t;
    int c = (i < nn) ? g_counts[i] : 0;
    s[t] = c;
    __syncthreads();
    for (int off = 1; off < 1024; off <<= 1) {
        int v = (t >= off) ? s[t - off] : 0;
        __syncthreads();
        s[t] += v;
        __syncthreads();
    }
    if (i < nn) g_rowptr[i] = s[t];
    if (t == 1023) g_blocksums[blockIdx.x] = s[1023];
}

__global__ void scan3_kernel(int nn, int ee, int nb) {
    __shared__ int bs[128];
    int t = threadIdx.x;
    if (t < 128) bs[t] = (t < nb) ? g_blocksums[t] : 0;
    __syncthreads();
    for (int off = 1; off < 128; off <<= 1) {
        int v = (t >= off && t < 128) ? bs[t - off] : 0;
        __syncthreads();
        if (t < 128) bs[t] += v;
        __syncthreads();
    }
    int base = (blockIdx.x == 0) ? 0 : bs[blockIdx.x - 1];

    int i = blockIdx.x * 1024 + t;
    if (i < nn) {
        int c = g_counts[i];
        g_counts[i] = 0;
        int excl = g_rowptr[i] - c + base;
        g_rowptr[i] = excl;
        g_cursor[i] = excl;
        g_dinv[i] = rsqrtf((float)(c + 1));  // +1 self loop
    }
    if (i == 0) g_rowptr[nn] = ee;
}

__global__ void fill_kernel(const int* __restrict__ src, const int* __restrict__ dst, int ee) {
    int e = blockIdx.x * blockDim.x + threadIdx.x;
    if (e < ee) {
        int pos = atomicAdd(&g_cursor[dst[e]], 1);
        g_esrc[pos] = src[e];
    }
}

// ---------------- GEMM via tensor cores (split-bf16, 3 MMAs) ----------------
// g_tmp[n,:] = (act(X)[n,:] @ W^T) * dinv[n].
// BM=128, BN=64, BK=32; 256 threads = 8 warps; warp tile 32x32 (2x4 m16n8k16).
// X,W split into bf16 hi+lo in smem; D = hi*hi + hi*lo + lo*hi (fp32 accum).
template <int DIN, bool USE_GH, bool APPLY_ACT>
__global__ __launch_bounds__(256)
void gemm_scale_kernel(const float* __restrict__ Xin,
                       const float* __restrict__ W, int nn) {
    const float* __restrict__ X = USE_GH ? (const float*)g_h : Xin;
    const int NST = DIN / 32;

    // rows padded to 40 bf16 (80 bytes): 16B-aligned, ldmatrix conflict-spread
    __shared__ __align__(16) __nv_bfloat162 AsHi[128][20];
    __shared__ __align__(16) __nv_bfloat162 AsLo[128][20];
    __shared__ __align__(16) __nv_bfloat162 BsHi[64][20];
    __shared__ __align__(16) __nv_bfloat162 BsLo[64][20];
    __shared__ float s_sc[DH];
    __shared__ float s_sh[DH];

    int tid = threadIdx.x;
    int lane = tid & 31;
    int wid = tid >> 5;
    int br = blockIdx.x * 128;
    int m0w = (wid & 3) * 32;   // warp row base
    int n0w = (wid >> 2) * 32;  // warp col base

    if (APPLY_ACT) {
        if (tid < DH) { s_sc[tid] = g_scale[tid]; s_sh[tid] = g_shift[tid]; }
        __syncthreads();
    }

    unsigned int asHiB = smem_u32(AsHi);
    unsigned int asLoB = smem_u32(AsLo);
    unsigned int bsHiB = smem_u32(BsHi);
    unsigned int bsLoB = smem_u32(BsLo);

    float acc[2][4][4];
#pragma unroll
    for (int mi = 0; mi < 2; mi++) {
#pragma unroll
        for (int ni = 0; ni < 4; ni++) {
#pragma unroll
            for (int q = 0; q < 4; q++) acc[mi][ni][q] = 0.0f;
        }
    }

    int arow = tid >> 1;             // 0..127
    int aseg = (tid & 1) * 16;       // k offset 0/16
    int bj = tid & 63;
    int bkh = (tid >> 6) * 8;

    for (int s = 0; s < NST; s++) {
        int kb = s * 32;
        // ---- stage A (X) ----
        {
            int row = br + arow;
            bool ok = row < nn;
            const float* xr = X + (size_t)row * DIN + kb + aseg;
#pragma unroll
            for (int kk = 0; kk < 4; kk++) {
                float4 v = ok ? *(const float4*)(xr + kk * 4)
                              : make_float4(0.f, 0.f, 0.f, 0.f);
                if (APPLY_ACT && ok) {
                    int k0 = kb + aseg + kk * 4;
                    v.x = gelu_f(v.x * s_sc[k0 + 0] + s_sh[k0 + 0]);
                    v.y = gelu_f(v.y * s_sc[k0 + 1] + s_sh[k0 + 1]);
                    v.z = gelu_f(v.z * s_sc[k0 + 2] + s_sh[k0 + 2]);
                    v.w = gelu_f(v.w * s_sc[k0 + 3] + s_sh[k0 + 3]);
                }
                __nv_bfloat16 hx = __float2bfloat16(v.x);
                __nv_bfloat16 hy = __float2bfloat16(v.y);
                __nv_bfloat16 hz = __float2bfloat16(v.z);
                __nv_bfloat16 hw = __float2bfloat16(v.w);
                __nv_bfloat16 lx = __float2bfloat16(v.x - __bfloat162float(hx));
                __nv_bfloat16 ly = __float2bfloat16(v.y - __bfloat162float(hy));
                __nv_bfloat16 lz = __float2bfloat16(v.z - __bfloat162float(hz));
                __nv_bfloat16 lw = __float2bfloat16(v.w - __bfloat162float(hw));
                int cc = (aseg >> 1) + kk * 2;
                AsHi[arow][cc]     = __halves2bfloat162(hx, hy);
                AsHi[arow][cc + 1] = __halves2bfloat162(hz, hw);
                AsLo[arow][cc]     = __halves2bfloat162(lx, ly);
                AsLo[arow][cc + 1] = __halves2bfloat162(lz, lw);
            }
        }
        // ---- stage B (W) ----
        {
            const float* wr = W + (size_t)bj * DIN + kb + bkh;
#pragma unroll
            for (int kk = 0; kk < 2; kk++) {
                float4 v = *(const float4*)(wr + kk * 4);
                __nv_bfloat16 hx = __float2bfloat16(v.x);
                __nv_bfloat16 hy = __float2bfloat16(v.y);
                __nv_bfloat16 hz = __float2bfloat16(v.z);
                __nv_bfloat16 hw = __float2bfloat16(v.w);
                __nv_bfloat16 lx = __float2bfloat16(v.x - __bfloat162float(hx));
                __nv_bfloat16 ly = __float2bfloat16(v.y - __bfloat162float(hy));
                __nv_bfloat16 lz = __float2bfloat16(v.z - __bfloat162float(hz));
                __nv_bfloat16 lw = __float2bfloat16(v.w - __bfloat162float(hw));
                int cc = (bkh >> 1) + kk * 2;
                BsHi[bj][cc]     = __halves2bfloat162(hx, hy);
                BsHi[bj][cc + 1] = __halves2bfloat162(hz, hw);
                BsLo[bj][cc]     = __halves2bfloat162(lx, ly);
                BsLo[bj][cc + 1] = __halves2bfloat162(lz, lw);
            }
        }
        __syncthreads();

        // ---- 2 k16 steps per stage ----
#pragma unroll
        for (int ks = 0; ks < 2; ks++) {
            unsigned int ahi[2][4];
            unsigned int alo[2][4];
#pragma unroll
            for (int mi = 0; mi < 2; mi++) {
                unsigned int roff =
                    (unsigned int)(m0w + mi * 16 + (lane & 15)) * 80u +
                    (unsigned int)(ks * 16 + ((lane >> 4) << 3)) * 2u;
                ldmat4(ahi[mi][0], ahi[mi][1], ahi[mi][2], ahi[mi][3], asHiB + roff);
                ldmat4(alo[mi][0], alo[mi][1], alo[mi][2], alo[mi][3], asLoB + roff);
            }
            unsigned int bhi[2][4];
            unsigned int blo[2][4];
#pragma unroll
            for (int pi = 0; pi < 2; pi++) {
                unsigned int roff =
                    (unsigned int)(n0w + pi * 16 + (((lane >> 4) & 1) << 3) +
                                   (lane & 7)) * 80u +
                    (unsigned int)(ks * 16 + (((lane >> 3) & 1) << 3)) * 2u;
                ldmat4(bhi[pi][0], bhi[pi][1], bhi[pi][2], bhi[pi][3], bsHiB + roff);
                ldmat4(blo[pi][0], blo[pi][1], blo[pi][2], blo[pi][3], bsLoB + roff);
            }
#pragma unroll
            for (int mi = 0; mi < 2; mi++) {
#pragma unroll
                for (int ni = 0; ni < 4; ni++) {
                    int pi = ni >> 1;
                    int sel = (ni & 1) * 2;
                    mma16816(acc[mi][ni], ahi[mi], bhi[pi][sel], bhi[pi][sel + 1]);
                    mma16816(acc[mi][ni], ahi[mi], blo[pi][sel], blo[pi][sel + 1]);
                    mma16816(acc[mi][ni], alo[mi], bhi[pi][sel], bhi[pi][sel + 1]);
                }
            }
        }
        __syncthreads();
    }

    // ---- epilogue: scale by dinv, store fp32 ----
#pragma unroll
    for (int mi = 0; mi < 2; mi++) {
        int r0 = br + m0w + mi * 16 + (lane >> 2);
        int r1 = r0 + 8;
        float dv0 = (r0 < nn) ? g_dinv[r0] : 0.0f;
        float dv1 = (r1 < nn) ? g_dinv[r1] : 0.0f;
#pragma unroll
        for (int ni = 0; ni < 4; ni++) {
            int c = n0w + ni * 8 + (lane & 3) * 2;
            if (r0 < nn) {
                float2 o = make_float2(acc[mi][ni][0] * dv0, acc[mi][ni][1] * dv0);
                *(float2*)&g_tmp[(size_t)r0 * DH + c] = o;
            }
            if (r1 < nn) {
                float2 o = make_float2(acc[mi][ni][2] * dv1, acc[mi][ni][3] * dv1);
                *(float2*)&g_tmp[(size_t)r1 * DH + c] = o;
            }
        }
    }
}

// ---------------- gather-aggregate + bias + BN stats (R10 fp32 form) ----------------
__global__ void gather_kernel(const float* __restrict__ bias, int nn) {
    __shared__ float ss[DH];
    __shared__ float sq[DH];
    int tid = threadIdx.x;
    if (tid < DH) { ss[tid] = 0.0f; sq[tid] = 0.0f; }
    __syncthreads();

    const float2* __restrict__ tmp2 = (const float2*)g_tmp;
    float2* __restrict__ h2 = (float2*)g_h;

    int lane = tid & 31;
    int warp = blockIdx.x * (blockDim.x >> 5) + (tid >> 5);
    int nwarps = gridDim.x * (blockDim.x >> 5);

    float bx = bias[2 * lane];
    float by = bias[2 * lane + 1];
    float s0 = 0.f, s1 = 0.f, q0 = 0.f, q1 = 0.f;

    for (int n = warp; n < nn; n += nwarps) {
        int st = g_rowptr[n];
        int en = g_rowptr[n + 1];
        float2 self = tmp2[n * 32 + lane];
        float ax = self.x, ay = self.y;
        int e = st;
        for (; e < en && (e & 3); e++) {
            float2 v = tmp2[g_esrc[e] * 32 + lane];
            ax += v.x; ay += v.y;
        }
        for (; e + 8 <= en; e += 8) {
            int4 i0 = *(const int4*)&g_esrc[e];
            int4 i1 = *(const int4*)&g_esrc[e + 4];
            float2 v0 = tmp2[i0.x * 32 + lane];
            float2 v1 = tmp2[i0.y * 32 + lane];
            float2 v2 = tmp2[i0.z * 32 + lane];
            float2 v3 = tmp2[i0.w * 32 + lane];
            float2 v4 = tmp2[i1.x * 32 + lane];
            float2 v5 = tmp2[i1.y * 32 + lane];
            float2 v6 = tmp2[i1.z * 32 + lane];
            float2 v7 = tmp2[i1.w * 32 + lane];
            ax += ((v0.x + v1.x) + (v2.x + v3.x)) + ((v4.x + v5.x) + (v6.x + v7.x));
            ay += ((v0.y + v1.y) + (v2.y + v3.y)) + ((v4.y + v5.y) + (v6.y + v7.y));
        }
        for (; e < en; e++) {
            float2 v = tmp2[g_esrc[e] * 32 + lane];
            ax += v.x; ay += v.y;
        }
        float dv = g_dinv[n];
        float rx = ax * dv + bx;
        float ry = ay * dv + by;
        h2[n * 32 + lane] = make_float2(rx, ry);
        s0 += rx; q0 += rx * rx;
        s1 += ry; q1 += ry * ry;
    }

    atomicAdd(&ss[2 * lane], s0);
    atomicAdd(&ss[2 * lane + 1], s1);
    atomicAdd(&sq[2 * lane], q0);
    atomicAdd(&sq[2 * lane + 1], q1);
    __syncthreads();
    if (tid < DH) {
        atomicAdd(&g_sums[tid], ss[tid]);
        atomicAdd(&g_sumsq[tid], sq[tid]);
    }
}

// ---------------- BN stats -> scale/shift; re-zero stats ----------------
__global__ void stats_final_kernel(const float* __restrict__ gamma,
                                   const float* __restrict__ beta, float invN) {
    int j = threadIdx.x;  // 64 threads
    float mean = g_sums[j] * invN;
    float var = g_sumsq[j] * invN - mean * mean;
    float sc = gamma[j] * rsqrtf(var + 1e-5f);
    g_scale[j] = sc;
    g_shift[j] = beta[j] - mean * sc;
    g_sums[j] = 0.0f;
    g_sumsq[j] = 0.0f;
}

// ---------------- final: out = act(h) @ Wf^T + bf  (64 -> 10) ----------------
__global__ void final_kernel(const float* __restrict__ Wf, const float* __restrict__ bf,
                             float* __restrict__ out, int nn) {
    __shared__ float Hs[64][65];
    __shared__ float Ws[10][64];
    __shared__ float s_sc[DH];
    __shared__ float s_sh[DH];
    int tid = threadIdx.x;  // 128 threads
    int br = blockIdx.x * 64;

    if (tid < DH) { s_sc[tid] = g_scale[tid]; s_sh[tid] = g_shift[tid]; }
    __syncthreads();

    for (int idx = tid; idx < 64 * 64; idx += 128) {
        int n = idx >> 6;
        int k = idx & 63;
        int row = br + n;
        float v = (row < nn) ? g_h[row * DH + k] : 0.0f;
        Hs[n][k] = gelu_f(v * s_sc[k] + s_sh[k]);
    }
    for (int idx = tid; idx < 640; idx += 128) {
        Ws[idx >> 6][idx & 63] = Wf[idx];
    }
    __syncthreads();

    int nl = tid & 63;
    int c0 = (tid >> 6) * 5;
    float acc[5];
#pragma unroll
    for (int c = 0; c < 5; c++) acc[c] = bf[c0 + c];
#pragma unroll 16
    for (int k = 0; k < 64; k++) {
        float hv = Hs[nl][k];
#pragma unroll
        for (int c = 0; c < 5; c++) acc[c] += hv * Ws[c0 + c][k];
    }
    int row = br + nl;
    if (row < nn) {
#pragma unroll
        for (int c = 0; c < 5; c++) out[row * 10 + c0 + c] = acc[c];
    }
}

// ---------------- host orchestration ----------------
extern "C" void kernel_launch(void* const* d_in, const int* in_sizes, int n_in,
                              void* d_out, int out_size) {
    const float* x  = (const float*)d_in[0];
    const int*   ei = (const int*)d_in[1];
    const float* W1 = (const float*)d_in[2];
    const float* b1 = (const float*)d_in[3];
    const float* g1 = (const float*)d_in[4];
    const float* be1 = (const float*)d_in[5];
    const float* W2 = (const float*)d_in[6];
    const float* b2 = (const float*)d_in[7];
    const float* g2 = (const float*)d_in[8];
    const float* be2 = (const float*)d_in[9];
    const float* W3 = (const float*)d_in[10];
    const float* b3 = (const float*)d_in[11];
    const float* g3 = (const float*)d_in[12];
    const float* be3 = (const float*)d_in[13];
    const float* Wf = (const float*)d_in[14];
    const float* bf = (const float*)d_in[15];
    float* out = (float*)d_out;

    int nn = in_sizes[0] / 128;      // 100000
    int ee = in_sizes[1] / 2;        // 1600000
    const int* src = ei;
    const int* dst = ei + ee;

    int nb_e = (ee + 255) / 256;
    int nb_scan = (nn + 1023) / 1024;
    float invN = 1.0f / (float)nn;

    int gemm_blocks = (nn + 127) / 128;
    int out_blocks = (nn + 63) / 64;
    int gather_blocks = 1184;

    // ---- CSR build (counts/stats pre-zeroed: self-restoring invariants) ----
    hist_kernel<<<nb_e, 256>>>(dst, ee);
    scan1_kernel<<<nb_scan, 1024>>>(nn);
    scan3_kernel<<<nb_scan, 1024>>>(nn, ee, nb_scan);

    // ---- layer 1 (128 -> 64) ----
    gemm_scale_kernel<128, false, false><<<gemm_blocks, 256>>>(x, W1, nn);
    fill_kernel<<<nb_e, 256>>>(src, dst, ee);
    gather_kernel<<<gather_blocks, 256>>>(b1, nn);
    stats_final_kernel<<<1, 64>>>(g1, be1, invN);

    // ---- layer 2 (64 -> 64): BN1+GELU fused into X staging ----
    gemm_scale_kernel<64, true, true><<<gemm_blocks, 256>>>(nullptr, W2, nn);
    gather_kernel<<<gather_blocks, 256>>>(b2, nn);
    stats_final_kernel<<<1, 64>>>(g2, be2, invN);

    // ---- layer 3 (64 -> 64): BN2+GELU fused into X staging ----
    gemm_scale_kernel<64, true, true><<<gemm_blocks, 256>>>(nullptr, W3, nn);
    gather_kernel<<<gather_blocks, 256>>>(b3, nn);
    stats_final_kernel<<<1, 64>>>(g3, be3, invN);

    // ---- final classifier (64 -> 10): BN3+GELU fused into H load ----
    final_kernel<<<out_blocks, 128>>>(Wf, bf, out, nn);
}

// round 14
// speedup vs baseline: 1.1804x; 1.0101x over previous
#include <cuda_runtime.h>
#include <cuda_bf16.h>
#include <cstdint>
#include <math.h>

#define NN_MAX 100000
#define EE_MAX 1600000
#define DH 64

// ---------------- device scratch ----------------
__device__ float g_tmp[NN_MAX * DH];   // fp32 messages: (act(X) @ W^T) * dinv
__device__ float g_h[NN_MAX * DH];     // layer activations (pre-BN, post-bias)
__device__ float g_dinv[NN_MAX];
__device__ int   g_counts[NN_MAX];     // zeroed by scan3 after use (self-restoring)
__device__ int   g_rowptr[NN_MAX + 1];
__device__ int   g_cursor[NN_MAX];
__device__ int   g_esrc[EE_MAX];
__device__ int   g_blocksums[128];
__device__ float g_sums[3 * DH];       // per-layer BN sums (zeroed by hist_kernel)
__device__ float g_sumsq[3 * DH];

__device__ __forceinline__ float gelu_f(float v) {
    return 0.5f * v * (1.0f + erff(v * 0.70710678118654752440f));
}

__device__ __forceinline__ unsigned int smem_u32(const void* p) {
    unsigned int a;
    asm("{ .reg .u64 t; cvta.to.shared.u64 t, %1; cvt.u32.u64 %0, t; }"
        : "=r"(a) : "l"(p));
    return a;
}

__device__ __forceinline__ void ldmat4(unsigned int& r0, unsigned int& r1,
                                       unsigned int& r2, unsigned int& r3,
                                       unsigned int addr) {
    asm volatile("ldmatrix.sync.aligned.m8n8.x4.shared.b16 {%0,%1,%2,%3}, [%4];"
                 : "=r"(r0), "=r"(r1), "=r"(r2), "=r"(r3) : "r"(addr));
}

__device__ __forceinline__ void mma16816(float* c, const unsigned int* a,
                                         unsigned int b0, unsigned int b1) {
    asm volatile(
        "mma.sync.aligned.m16n8k16.row.col.f32.bf16.bf16.f32 "
        "{%0,%1,%2,%3}, {%4,%5,%6,%7}, {%8,%9}, {%0,%1,%2,%3};"
        : "+f"(c[0]), "+f"(c[1]), "+f"(c[2]), "+f"(c[3])
        : "r"(a[0]), "r"(a[1]), "r"(a[2]), "r"(a[3]), "r"(b0), "r"(b1));
}

__device__ __forceinline__ unsigned int bf2pack(float x, float y) {
    __nv_bfloat162 t = __halves2bfloat162(__float2bfloat16(x), __float2bfloat16(y));
    return *(unsigned int*)&t;
}

// ---------------- CSR build ----------------
// hist also zeroes the per-layer BN stats for this call (block 0).
__global__ void hist_kernel(const int* __restrict__ dst, int ee) {
    if (blockIdx.x == 0 && threadIdx.x < 3 * DH) {
        g_sums[threadIdx.x] = 0.0f;
        g_sumsq[threadIdx.x] = 0.0f;
    }
    int e = blockIdx.x * blockDim.x + threadIdx.x;
    if (e < ee) atomicAdd(&g_counts[dst[e]], 1);
}

__global__ void scan1_kernel(int nn) {
    __shared__ int s[1024];
    int t = threadIdx.x;
    int i = blockIdx.x * 1024 + t;
    int c = (i < nn) ? g_counts[i] : 0;
    s[t] = c;
    __syncthreads();
    for (int off = 1; off < 1024; off <<= 1) {
        int v = (t >= off) ? s[t - off] : 0;
        __syncthreads();
        s[t] += v;
        __syncthreads();
    }
    if (i < nn) g_rowptr[i] = s[t];
    if (t == 1023) g_blocksums[blockIdx.x] = s[1023];
}

__global__ void scan3_kernel(int nn, int ee, int nb) {
    __shared__ int bs[128];
    int t = threadIdx.x;
    if (t < 128) bs[t] = (t < nb) ? g_blocksums[t] : 0;
    __syncthreads();
    for (int off = 1; off < 128; off <<= 1) {
        int v = (t >= off && t < 128) ? bs[t - off] : 0;
        __syncthreads();
        if (t < 128) bs[t] += v;
        __syncthreads();
    }
    int base = (blockIdx.x == 0) ? 0 : bs[blockIdx.x - 1];

    int i = blockIdx.x * 1024 + t;
    if (i < nn) {
        int c = g_counts[i];
        g_counts[i] = 0;
        int excl = g_rowptr[i] - c + base;
        g_rowptr[i] = excl;
        g_cursor[i] = excl;
        g_dinv[i] = rsqrtf((float)(c + 1));  // +1 self loop
    }
    if (i == 0) g_rowptr[nn] = ee;
}

__global__ void fill_kernel(const int* __restrict__ src, const int* __restrict__ dst, int ee) {
    int e = blockIdx.x * blockDim.x + threadIdx.x;
    if (e < ee) {
        int pos = atomicAdd(&g_cursor[dst[e]], 1);
        g_esrc[pos] = src[e];
    }
}

// ---------------- GEMM via tensor cores (split-bf16, 3 MMAs) ----------------
// g_tmp[n,:] = (act(X)[n,:] @ W^T) * dinv[n].
// BM=128, BN=64, BK=32; 256 threads = 8 warps; warp tile 32x32 (2x4 m16n8k16).
// Staging uses STS.128 (uint4) for the hi/lo bf16 tiles.
// APPLY_ACT: BN scale/shift computed in-block from g_sums[layer-1] + gamma/beta.
template <int DIN, bool USE_GH, bool APPLY_ACT>
__global__ __launch_bounds__(256)
void gemm_scale_kernel(const float* __restrict__ Xin,
                       const float* __restrict__ W, int nn,
                       const float* __restrict__ gamma,
                       const float* __restrict__ beta,
                       float invN, int statsIdx) {
    const float* __restrict__ X = USE_GH ? (const float*)g_h : Xin;
    const int NST = DIN / 32;

    // rows padded to 40 bf16 (80 bytes): 16B-aligned rows, conflict-spread
    __shared__ __align__(16) __nv_bfloat162 AsHi[128][20];
    __shared__ __align__(16) __nv_bfloat162 AsLo[128][20];
    __shared__ __align__(16) __nv_bfloat162 BsHi[64][20];
    __shared__ __align__(16) __nv_bfloat162 BsLo[64][20];
    __shared__ float s_sc[DH];
    __shared__ float s_sh[DH];

    int tid = threadIdx.x;
    int lane = tid & 31;
    int wid = tid >> 5;
    int br = blockIdx.x * 128;
    int m0w = (wid & 3) * 32;   // warp row base
    int n0w = (wid >> 2) * 32;  // warp col base

    if (APPLY_ACT) {
        if (tid < DH) {
            float mean = g_sums[statsIdx * DH + tid] * invN;
            float var = g_sumsq[statsIdx * DH + tid] * invN - mean * mean;
            float sc = gamma[tid] * rsqrtf(var + 1e-5f);
            s_sc[tid] = sc;
            s_sh[tid] = beta[tid] - mean * sc;
        }
        __syncthreads();
    }

    unsigned int asHiB = smem_u32(AsHi);
    unsigned int asLoB = smem_u32(AsLo);
    unsigned int bsHiB = smem_u32(BsHi);
    unsigned int bsLoB = smem_u32(BsLo);

    float acc[2][4][4];
#pragma unroll
    for (int mi = 0; mi < 2; mi++) {
#pragma unroll
        for (int ni = 0; ni < 4; ni++) {
#pragma unroll
            for (int q = 0; q < 4; q++) acc[mi][ni][q] = 0.0f;
        }
    }

    int arow = tid >> 1;             // 0..127
    int aseg = (tid & 1) * 16;       // k offset 0/16
    int bj = tid & 63;
    int bkh = (tid >> 6) * 8;

    for (int s = 0; s < NST; s++) {
        int kb = s * 32;
        // ---- stage A (X): 2 halves x (LDG x2, STS.128 hi+lo) ----
        {
            int row = br + arow;
            bool ok = row < nn;
            const float* xr = X + (size_t)row * DIN + kb + aseg;
            char* rowHi = (char*)&AsHi[arow][0] + aseg * 2;
            char* rowLo = (char*)&AsLo[arow][0] + aseg * 2;
#pragma unroll
            for (int half = 0; half < 2; half++) {
                unsigned int hw_[4];
                unsigned int lw_[4];
#pragma unroll
                for (int kk2 = 0; kk2 < 2; kk2++) {
                    int kk = half * 2 + kk2;
                    float4 v = ok ? *(const float4*)(xr + kk * 4)
                                  : make_float4(0.f, 0.f, 0.f, 0.f);
                    if (APPLY_ACT && ok) {
                        int k0 = kb + aseg + kk * 4;
                        v.x = gelu_f(v.x * s_sc[k0 + 0] + s_sh[k0 + 0]);
                        v.y = gelu_f(v.y * s_sc[k0 + 1] + s_sh[k0 + 1]);
                        v.z = gelu_f(v.z * s_sc[k0 + 2] + s_sh[k0 + 2]);
                        v.w = gelu_f(v.w * s_sc[k0 + 3] + s_sh[k0 + 3]);
                    }
                    float hx = __bfloat162float(__float2bfloat16(v.x));
                    float hy = __bfloat162float(__float2bfloat16(v.y));
                    float hz = __bfloat162float(__float2bfloat16(v.z));
                    float hw = __bfloat162float(__float2bfloat16(v.w));
                    hw_[kk2 * 2 + 0] = bf2pack(hx, hy);
                    hw_[kk2 * 2 + 1] = bf2pack(hz, hw);
                    lw_[kk2 * 2 + 0] = bf2pack(v.x - hx, v.y - hy);
                    lw_[kk2 * 2 + 1] = bf2pack(v.z - hz, v.w - hw);
                }
                *(uint4*)(rowHi + half * 16) = make_uint4(hw_[0], hw_[1], hw_[2], hw_[3]);
                *(uint4*)(rowLo + half * 16) = make_uint4(lw_[0], lw_[1], lw_[2], lw_[3]);
            }
        }
        // ---- stage B (W): one STS.128 per array ----
        {
            const float* wr = W + (size_t)bj * DIN + kb + bkh;
            unsigned int hw_[4];
            unsigned int lw_[4];
#pragma unroll
            for (int kk = 0; kk < 2; kk++) {
                float4 v = *(const float4*)(wr + kk * 4);
                float hx = __bfloat162float(__float2bfloat16(v.x));
                float hy = __bfloat162float(__float2bfloat16(v.y));
                float hz = __bfloat162float(__float2bfloat16(v.z));
                float hw = __bfloat162float(__float2bfloat16(v.w));
                hw_[kk * 2 + 0] = bf2pack(hx, hy);
                hw_[kk * 2 + 1] = bf2pack(hz, hw);
                lw_[kk * 2 + 0] = bf2pack(v.x - hx, v.y - hy);
                lw_[kk * 2 + 1] = bf2pack(v.z - hz, v.w - hw);
            }
            *(uint4*)((char*)&BsHi[bj][0] + bkh * 2) =
                make_uint4(hw_[0], hw_[1], hw_[2], hw_[3]);
            *(uint4*)((char*)&BsLo[bj][0] + bkh * 2) =
                make_uint4(lw_[0], lw_[1], lw_[2], lw_[3]);
        }
        __syncthreads();

        // ---- 2 k16 steps per stage ----
#pragma unroll
        for (int ks = 0; ks < 2; ks++) {
            unsigned int ahi[2][4];
            unsigned int alo[2][4];
#pragma unroll
            for (int mi = 0; mi < 2; mi++) {
                unsigned int roff =
                    (unsigned int)(m0w + mi * 16 + (lane & 15)) * 80u +
                    (unsigned int)(ks * 16 + ((lane >> 4) << 3)) * 2u;
                ldmat4(ahi[mi][0], ahi[mi][1], ahi[mi][2], ahi[mi][3], asHiB + roff);
                ldmat4(alo[mi][0], alo[mi][1], alo[mi][2], alo[mi][3], asLoB + roff);
            }
            unsigned int bhi[2][4];
            unsigned int blo[2][4];
#pragma unroll
            for (int pi = 0; pi < 2; pi++) {
                unsigned int roff =
                    (unsigned int)(n0w + pi * 16 + (((lane >> 4) & 1) << 3) +
                                   (lane & 7)) * 80u +
                    (unsigned int)(ks * 16 + (((lane >> 3) & 1) << 3)) * 2u;
                ldmat4(bhi[pi][0], bhi[pi][1], bhi[pi][2], bhi[pi][3], bsHiB + roff);
                ldmat4(blo[pi][0], blo[pi][1], blo[pi][2], blo[pi][3], bsLoB + roff);
            }
#pragma unroll
            for (int mi = 0; mi < 2; mi++) {
#pragma unroll
                for (int ni = 0; ni < 4; ni++) {
                    int pi = ni >> 1;
                    int sel = (ni & 1) * 2;
                    mma16816(acc[mi][ni], ahi[mi], bhi[pi][sel], bhi[pi][sel + 1]);
                    mma16816(acc[mi][ni], ahi[mi], blo[pi][sel], blo[pi][sel + 1]);
                    mma16816(acc[mi][ni], alo[mi], bhi[pi][sel], bhi[pi][sel + 1]);
                }
            }
        }
        __syncthreads();
    }

    // ---- epilogue: scale by dinv, store fp32 ----
#pragma unroll
    for (int mi = 0; mi < 2; mi++) {
        int r0 = br + m0w + mi * 16 + (lane >> 2);
        int r1 = r0 + 8;
        float dv0 = (r0 < nn) ? g_dinv[r0] : 0.0f;
        float dv1 = (r1 < nn) ? g_dinv[r1] : 0.0f;
#pragma unroll
        for (int ni = 0; ni < 4; ni++) {
            int c = n0w + ni * 8 + (lane & 3) * 2;
            if (r0 < nn) {
                float2 o = make_float2(acc[mi][ni][0] * dv0, acc[mi][ni][1] * dv0);
                *(float2*)&g_tmp[(size_t)r0 * DH + c] = o;
            }
            if (r1 < nn) {
                float2 o = make_float2(acc[mi][ni][2] * dv1, acc[mi][ni][3] * dv1);
                *(float2*)&g_tmp[(size_t)r1 * DH + c] = o;
            }
        }
    }
}

// ---------------- gather-aggregate + bias + BN stats (layer-indexed) ----------------
__global__ void gather_kernel(const float* __restrict__ bias, int nn, int statsIdx) {
    __shared__ float ss[DH];
    __shared__ float sq[DH];
    int tid = threadIdx.x;
    if (tid < DH) { ss[tid] = 0.0f; sq[tid] = 0.0f; }
    __syncthreads();

    const float2* __restrict__ tmp2 = (const float2*)g_tmp;
    float2* __restrict__ h2 = (float2*)g_h;

    int lane = tid & 31;
    int warp = blockIdx.x * (blockDim.x >> 5) + (tid >> 5);
    int nwarps = gridDim.x * (blockDim.x >> 5);

    float bx = bias[2 * lane];
    float by = bias[2 * lane + 1];
    float s0 = 0.f, s1 = 0.f, q0 = 0.f, q1 = 0.f;

    for (int n = warp; n < nn; n += nwarps) {
        int st = g_rowptr[n];
        int en = g_rowptr[n + 1];
        float2 self = tmp2[n * 32 + lane];
        float ax = self.x, ay = self.y;
        int e = st;
        for (; e < en && (e & 3); e++) {
            float2 v = tmp2[g_esrc[e] * 32 + lane];
            ax += v.x; ay += v.y;
        }
        for (; e + 8 <= en; e += 8) {
            int4 i0 = *(const int4*)&g_esrc[e];
            int4 i1 = *(const int4*)&g_esrc[e + 4];
            float2 v0 = tmp2[i0.x * 32 + lane];
            float2 v1 = tmp2[i0.y * 32 + lane];
            float2 v2 = tmp2[i0.z * 32 + lane];
            float2 v3 = tmp2[i0.w * 32 + lane];
            float2 v4 = tmp2[i1.x * 32 + lane];
            float2 v5 = tmp2[i1.y * 32 + lane];
            float2 v6 = tmp2[i1.z * 32 + lane];
            float2 v7 = tmp2[i1.w * 32 + lane];
            ax += ((v0.x + v1.x) + (v2.x + v3.x)) + ((v4.x + v5.x) + (v6.x + v7.x));
            ay += ((v0.y + v1.y) + (v2.y + v3.y)) + ((v4.y + v5.y) + (v6.y + v7.y));
        }
        for (; e < en; e++) {
            float2 v = tmp2[g_esrc[e] * 32 + lane];
            ax += v.x; ay += v.y;
        }
        float dv = g_dinv[n];
        float rx = ax * dv + bx;
        float ry = ay * dv + by;
        h2[n * 32 + lane] = make_float2(rx, ry);
        s0 += rx; q0 += rx * rx;
        s1 += ry; q1 += ry * ry;
    }

    atomicAdd(&ss[2 * lane], s0);
    atomicAdd(&ss[2 * lane + 1], s1);
    atomicAdd(&sq[2 * lane], q0);
    atomicAdd(&sq[2 * lane + 1], q1);
    __syncthreads();
    if (tid < DH) {
        atomicAdd(&g_sums[statsIdx * DH + tid], ss[tid]);
        atomicAdd(&g_sumsq[statsIdx * DH + tid], sq[tid]);
    }
}

// ---------------- final: out = act(h) @ Wf^T + bf  (64 -> 10) ----------------
__global__ void final_kernel(const float* __restrict__ Wf, const float* __restrict__ bf,
                             float* __restrict__ out, int nn,
                             const float* __restrict__ gamma,
                             const float* __restrict__ beta, float invN) {
    __shared__ float Hs[64][65];
    __shared__ float Ws[10][64];
    __shared__ float s_sc[DH];
    __shared__ float s_sh[DH];
    int tid = threadIdx.x;  // 128 threads
    int br = blockIdx.x * 64;

    if (tid < DH) {
        float mean = g_sums[2 * DH + tid] * invN;
        float var = g_sumsq[2 * DH + tid] * invN - mean * mean;
        float sc = gamma[tid] * rsqrtf(var + 1e-5f);
        s_sc[tid] = sc;
        s_sh[tid] = beta[tid] - mean * sc;
    }
    __syncthreads();

    for (int idx = tid; idx < 64 * 64; idx += 128) {
        int n = idx >> 6;
        int k = idx & 63;
        int row = br + n;
        float v = (row < nn) ? g_h[row * DH + k] : 0.0f;
        Hs[n][k] = gelu_f(v * s_sc[k] + s_sh[k]);
    }
    for (int idx = tid; idx < 640; idx += 128) {
        Ws[idx >> 6][idx & 63] = Wf[idx];
    }
    __syncthreads();

    int nl = tid & 63;
    int c0 = (tid >> 6) * 5;
    float acc[5];
#pragma unroll
    for (int c = 0; c < 5; c++) acc[c] = bf[c0 + c];
#pragma unroll 16
    for (int k = 0; k < 64; k++) {
        float hv = Hs[nl][k];
#pragma unroll
        for (int c = 0; c < 5; c++) acc[c] += hv * Ws[c0 + c][k];
    }
    int row = br + nl;
    if (row < nn) {
#pragma unroll
        for (int c = 0; c < 5; c++) out[row * 10 + c0 + c] = acc[c];
    }
}

// ---------------- host orchestration ----------------
extern "C" void kernel_launch(void* const* d_in, const int* in_sizes, int n_in,
                              void* d_out, int out_size) {
    const float* x  = (const float*)d_in[0];
    const int*   ei = (const int*)d_in[1];
    const float* W1 = (const float*)d_in[2];
    const float* b1 = (const float*)d_in[3];
    const float* g1 = (const float*)d_in[4];
    const float* be1 = (const float*)d_in[5];
    const float* W2 = (const float*)d_in[6];
    const float* b2 = (const float*)d_in[7];
    const float* g2 = (const float*)d_in[8];
    const float* be2 = (const float*)d_in[9];
    const float* W3 = (const float*)d_in[10];
    const float* b3 = (const float*)d_in[11];
    const float* g3 = (const float*)d_in[12];
    const float* be3 = (const float*)d_in[13];
    const float* Wf = (const float*)d_in[14];
    const float* bf = (const float*)d_in[15];
    float* out = (float*)d_out;

    int nn = in_sizes[0] / 128;      // 100000
    int ee = in_sizes[1] / 2;        // 1600000
    const int* src = ei;
    const int* dst = ei + ee;

    int nb_e = (ee + 255) / 256;
    int nb_scan = (nn + 1023) / 1024;
    float invN = 1.0f / (float)nn;

    int gemm_blocks = (nn + 127) / 128;
    int out_blocks = (nn + 63) / 64;
    int gather_blocks = 1184;

    // ---- CSR build (also zeroes BN stats for this call) ----
    hist_kernel<<<nb_e, 256>>>(dst, ee);
    scan1_kernel<<<nb_scan, 1024>>>(nn);
    scan3_kernel<<<nb_scan, 1024>>>(nn, ee, nb_scan);

    // ---- layer 1 (128 -> 64) ----
    gemm_scale_kernel<128, false, false><<<gemm_blocks, 256>>>(
        x, W1, nn, nullptr, nullptr, 0.0f, 0);
    fill_kernel<<<nb_e, 256>>>(src, dst, ee);
    gather_kernel<<<gather_blocks, 256>>>(b1, nn, 0);

    // ---- layer 2 (64 -> 64): BN1+GELU fused into X staging ----
    gemm_scale_kernel<64, true, true><<<gemm_blocks, 256>>>(
        nullptr, W2, nn, g1, be1, invN, 0);
    gather_kernel<<<gather_blocks, 256>>>(b2, nn, 1);

    // ---- layer 3 (64 -> 64): BN2+GELU fused into X staging ----
    gemm_scale_kernel<64, true, true><<<gemm_blocks, 256>>>(
        nullptr, W3, nn, g2, be2, invN, 1);
    gather_kernel<<<gather_blocks, 256>>>(b3, nn, 2);

    // ---- final classifier (64 -> 10): BN3+GELU fused into H load ----
    final_kernel<<<out_blocks, 128>>>(Wf, bf, out, nn, g3, be3, invN);
}